// round 14
// baseline (speedup 1.0000x reference)
#include <cuda_runtime.h>
#include <cuda_fp16.h>
#include <math.h>
#include <stdint.h>

#define N_NODES 50000
#define N_EDGES 800000
#define IN_DIM  512
#define HID     256
#define OUT_DIM 128

// ---------------- scratch (static device globals; no allocation) ----------------
__device__ __half   g_qh[N_NODES * HID];
__device__ __half   g_kh[N_NODES * HID];
__device__ __half   g_vh[N_NODES * HID];
__device__ float    g_s[N_NODES * HID];
__device__ float    g_h[N_NODES * HID];
__device__ __half   g_xch[N_NODES * IN_DIM];
__device__ __half   g_wch[4 * IN_DIM * HID];
__device__ __half   g_wch2[4 * HID * OUT_DIM];
__device__ float    g_w[N_EDGES];
__device__ int      g_deg[N_NODES];
__device__ int      g_off[N_NODES + 1];
__device__ int      g_cursor[N_NODES];
__device__ int      g_csrsrc[N_EDGES];
__device__ int      g_src[N_EDGES];
__device__ int      g_dst[N_EDGES];
__device__ float    g_buck[256];
__device__ int      g_is64;

// ---------------- edge-index dtype detection ----------------
__global__ void detect_idx_kernel(const long long* __restrict__ ei) {
    int stride = gridDim.x * blockDim.x;
    int bad = 0;
    for (int i = blockIdx.x * blockDim.x + threadIdx.x; i < N_EDGES; i += stride) {
        long long v = ei[i];
        if (v < 0 || v >= N_NODES) bad = 1;
    }
    if (__syncthreads_or(bad) && threadIdx.x == 0) atomicAnd(&g_is64, 0);
}

__global__ void cvt_count_kernel(const void* __restrict__ eiv) {
    const bool is64 = (g_is64 != 0);
    const long long* e64 = (const long long*)eiv;
    const int*       e32 = (const int*)eiv;
    int stride = gridDim.x * blockDim.x;
    for (int e = blockIdx.x * blockDim.x + threadIdx.x; e < N_EDGES; e += stride) {
        long long sv = is64 ? e64[e]           : (long long)e32[e];
        long long dv = is64 ? e64[N_EDGES + e] : (long long)e32[N_EDGES + e];
        int s = (int)sv, d = (int)dv;
        if (s < 0) s = 0; if (s >= N_NODES) s = N_NODES - 1;
        if (d < 0) d = 0; if (d >= N_NODES) d = N_NODES - 1;
        g_src[e] = s;
        g_dst[e] = d;
        atomicAdd(&g_deg[d], 1);
    }
}

__global__ void scan_offsets_kernel() {
    __shared__ int partial[1024];
    int t = threadIdx.x;
    const int C = (N_NODES + 1023) / 1024;
    int lo = t * C;
    int hi = lo + C; if (hi > N_NODES) hi = N_NODES;
    if (lo > N_NODES) lo = N_NODES;
    int s = 0;
    for (int i = lo; i < hi; i++) s += g_deg[i];
    partial[t] = s;
    __syncthreads();
    for (int o = 1; o < 1024; o <<= 1) {
        int add = (t >= o) ? partial[t - o] : 0;
        __syncthreads();
        partial[t] += add;
        __syncthreads();
    }
    int run = partial[t] - s;
    for (int i = lo; i < hi; i++) {
        g_off[i] = run;
        g_cursor[i] = run;
        run += g_deg[i];
    }
    if (t == 1023) g_off[N_NODES] = partial[1023];
}

__global__ void fill_csr_kernel() {
    int stride = gridDim.x * blockDim.x;
    for (int e = blockIdx.x * blockDim.x + threadIdx.x; e < N_EDGES; e += stride) {
        int p = atomicAdd(&g_cursor[g_dst[e]], 1);
        if (p >= 0 && p < N_EDGES) g_csrsrc[p] = g_src[e];
    }
}

// ---------------- fp16 pre-conversion ----------------
__global__ void cvt_f2h_kernel(const float* __restrict__ in, __half* __restrict__ out, int n) {
    int stride = gridDim.x * blockDim.x;
    for (int i = blockIdx.x * blockDim.x + threadIdx.x; i < n; i += stride)
        out[i] = __float2half(in[i]);
}

__global__ void cvtT4_f2h_kernel(const float* __restrict__ W0, const float* __restrict__ W1,
                                 const float* __restrict__ W2, const float* __restrict__ W3,
                                 __half* __restrict__ out, int K, int N) {
    const float* W;
    switch (blockIdx.y) {
        case 0: W = W0; break;
        case 1: W = W1; break;
        case 2: W = W2; break;
        default: W = W3; break;
    }
    __half* o = out + (long)blockIdx.y * K * N;
    int stride = gridDim.x * blockDim.x;
    int total = K * N;
    for (int i = blockIdx.x * blockDim.x + threadIdx.x; i < total; i += stride) {
        int k = i / N, n = i - k * N;
        o[n * K + k] = __float2half(W[i]);
    }
}

// ---------------- common MMA helpers ----------------
__device__ __forceinline__ void mma_f16(float* c, const unsigned* a, const unsigned* b) {
    asm volatile(
        "mma.sync.aligned.m16n8k16.row.col.f32.f16.f16.f32 "
        "{%0,%1,%2,%3}, {%4,%5,%6,%7}, {%8,%9}, {%0,%1,%2,%3};"
        : "+f"(c[0]), "+f"(c[1]), "+f"(c[2]), "+f"(c[3])
        : "r"(a[0]), "r"(a[1]), "r"(a[2]), "r"(a[3]), "r"(b[0]), "r"(b[1]));
}

__device__ __forceinline__ void ldsm_x4(unsigned* r, uint32_t saddr) {
    asm volatile("ldmatrix.sync.aligned.m8n8.x4.shared.b16 {%0,%1,%2,%3}, [%4];"
        : "=r"(r[0]), "=r"(r[1]), "=r"(r[2]), "=r"(r[3]) : "r"(saddr));
}

__device__ __forceinline__ void ldsm_x2(unsigned* r, uint32_t saddr) {
    asm volatile("ldmatrix.sync.aligned.m8n8.x2.shared.b16 {%0,%1}, [%2];"
        : "=r"(r[0]), "=r"(r[1]) : "r"(saddr));
}

__device__ __forceinline__ void cpasync16(void* smem, const void* gmem) {
    unsigned saddr = (unsigned)__cvta_generic_to_shared(smem);
    asm volatile("cp.async.ca.shared.global [%0], [%1], 16;" :: "r"(saddr), "l"(gmem));
}

#define HPAD 40
#define HSTAGES 4
#define GEMM_SMEM_BYTES  (HSTAGES * 2 * 128 * HPAD * 2)          // 128x128 variant
#define GEMM256_SMEM_BYTES (HSTAGES * (128 + 256) * HPAD * 2)    // 128x256 variant: 122880

// ---------------- GEMM A: 128x256 block tile, 64x64 warp tiles (layer 1) ----------------
// D[M,256] = A[M,K] @ Bt[256,K]^T + bias; z picks (Bt,bias,O); z<3 half out, z=3 float.
template <int K>
__global__ void __launch_bounds__(256, 1)
gemm4_f16_n256_kernel(const __half* __restrict__ A, const __half* __restrict__ BtAll,
                      const float* __restrict__ c0, const float* __restrict__ c1,
                      const float* __restrict__ c2, const float* __restrict__ c3,
                      void* __restrict__ O0, void* __restrict__ O1,
                      void* __restrict__ O2, void* __restrict__ O3, int M) {
    const int NTOT = 256;
    const float* bias; void* Ov;
    switch (blockIdx.z) {
        case 0: bias = c0; Ov = O0; break;
        case 1: bias = c1; Ov = O1; break;
        case 2: bias = c2; Ov = O2; break;
        default: bias = c3; Ov = O3; break;
    }
    const bool halfOut = (blockIdx.z < 3);
    const __half* Bt = BtAll + (long)blockIdx.z * NTOT * K;

    extern __shared__ __half hsm[];
    __half (*As)[128][HPAD] = (__half(*)[128][HPAD])hsm;
    __half (*Bs)[256][HPAD] = (__half(*)[256][HPAD])(hsm + HSTAGES * 128 * HPAD);

    int tid = threadIdx.x;
    int lane = tid & 31;
    int wid = tid >> 5;
    int wr = wid >> 2;          // 0..1: 64-row band
    int wc = wid & 3;           // 0..3: 64-col band
    int grp = lane >> 2;
    int qid = lane & 3;
    int bm = blockIdx.x * 128;

    float acc[4][8][4];
#pragma unroll
    for (int i = 0; i < 4; i++)
#pragma unroll
        for (int j = 0; j < 8; j++)
#pragma unroll
            for (int r = 0; r < 4; r++) acc[i][j][r] = 0.f;

    // cp.async: A 512 chunks (2/thread), B 1024 chunks (4/thread)
    int ar0 = tid >> 2,         ac0 = (tid & 3) * 8;
    int ar1 = (tid + 256) >> 2, ac1 = (tid & 3) * 8;
    int ag0 = bm + ar0; if (ag0 >= M) ag0 = M - 1;
    int ag1 = bm + ar1; if (ag1 >= M) ag1 = M - 1;

    // ldmatrix addressing
    int a_lrow = wr * 64 + (lane & 15);
    int a_lk   = 8 * (lane >> 4);
    // B x4: matrices (ni, klo), (ni, khi), (ni+1, klo), (ni+1, khi)
    int b_lcol = wc * 64 + (lane & 7) + ((lane >> 4) << 3);
    int b_lk   = 8 * ((lane >> 3) & 1);

    const int KT = K / 32;

#define PREFETCH(st, kt_) do { \
        int kb_ = (kt_) * 32; \
        cpasync16(&As[st][ar0][ac0], A + (long)ag0 * K + kb_ + ac0); \
        cpasync16(&As[st][ar1][ac1], A + (long)ag1 * K + kb_ + ac1); \
        _Pragma("unroll") \
        for (int u = 0; u < 4; u++) { \
            int idx = tid + u * 256; \
            int br = idx >> 2, bc = (idx & 3) * 8; \
            cpasync16(&Bs[st][br][bc], Bt + (long)br * K + kb_ + bc); \
        } \
        asm volatile("cp.async.commit_group;"); \
    } while (0)

    for (int st = 0; st < 3 && st < KT; st++) PREFETCH(st, st);

    for (int kt = 0; kt < KT; kt++) {
        int rem = KT - 1 - kt;
        if (rem >= 2)      asm volatile("cp.async.wait_group 2;");
        else if (rem == 1) asm volatile("cp.async.wait_group 1;");
        else               asm volatile("cp.async.wait_group 0;");
        __syncthreads();
        if (kt + 3 < KT) PREFETCH((kt + 3) & 3, kt + 3);
        int buf = kt & 3;

        uint32_t asb = (uint32_t)__cvta_generic_to_shared(&As[buf][0][0]);
        uint32_t bsb = (uint32_t)__cvta_generic_to_shared(&Bs[buf][0][0]);

#pragma unroll
        for (int ks = 0; ks < 32; ks += 16) {
            unsigned afr[4][4];
#pragma unroll
            for (int mi = 0; mi < 4; mi++)
                ldsm_x4(afr[mi], asb + ((a_lrow + mi * 16) * HPAD + ks + a_lk) * 2);
            unsigned bfr[4][4];
#pragma unroll
            for (int np = 0; np < 4; np++)
                ldsm_x4(bfr[np], bsb + ((b_lcol + np * 16) * HPAD + ks + b_lk) * 2);
#pragma unroll
            for (int mi = 0; mi < 4; mi++)
#pragma unroll
                for (int np = 0; np < 4; np++) {
                    mma_f16(acc[mi][2 * np],     afr[mi], &bfr[np][0]);
                    mma_f16(acc[mi][2 * np + 1], afr[mi], &bfr[np][2]);
                }
        }
        __syncthreads();
    }
#undef PREFETCH

#pragma unroll
    for (int mi = 0; mi < 4; mi++) {
        int r0 = bm + wr * 64 + mi * 16 + grp;
#pragma unroll
        for (int ni = 0; ni < 8; ni++) {
            int gc = wc * 64 + ni * 8 + 2 * qid;
            float bz0 = bias[gc], bz1 = bias[gc + 1];
            if (halfOut) {
                __half* Oh = (__half*)Ov;
                if (r0 < M)
                    *(__half2*)&Oh[(long)r0 * NTOT + gc] =
                        __floats2half2_rn(acc[mi][ni][0] + bz0, acc[mi][ni][1] + bz1);
                if (r0 + 8 < M)
                    *(__half2*)&Oh[(long)(r0 + 8) * NTOT + gc] =
                        __floats2half2_rn(acc[mi][ni][2] + bz0, acc[mi][ni][3] + bz1);
            } else {
                float* Of = (float*)Ov;
                if (r0 < M) {
                    Of[(long)r0 * NTOT + gc]     = acc[mi][ni][0] + bz0;
                    Of[(long)r0 * NTOT + gc + 1] = acc[mi][ni][1] + bz1;
                }
                if (r0 + 8 < M) {
                    Of[(long)(r0 + 8) * NTOT + gc]     = acc[mi][ni][2] + bz0;
                    Of[(long)(r0 + 8) * NTOT + gc + 1] = acc[mi][ni][3] + bz1;
                }
            }
        }
    }
}

// ---------------- GEMM B: 128x128 block tile (layer 2, N=128) ----------------
template <int NTOT, int K>
__global__ void __launch_bounds__(256, 2)
gemm4_f16_kernel(const __half* __restrict__ A, const __half* __restrict__ BtAll,
                 const float* __restrict__ c0, const float* __restrict__ c1,
                 const float* __restrict__ c2, const float* __restrict__ c3,
                 void* __restrict__ O0, void* __restrict__ O1,
                 void* __restrict__ O2, void* __restrict__ O3, int M) {
    const float* bias; void* Ov;
    switch (blockIdx.z) {
        case 0: bias = c0; Ov = O0; break;
        case 1: bias = c1; Ov = O1; break;
        case 2: bias = c2; Ov = O2; break;
        default: bias = c3; Ov = O3; break;
    }
    const bool halfOut = (blockIdx.z < 3);
    const __half* Bt = BtAll + (long)blockIdx.z * NTOT * K;

    extern __shared__ __half hsm[];
    __half (*As)[128][HPAD] = (__half(*)[128][HPAD])hsm;
    __half (*Bs)[128][HPAD] = (__half(*)[128][HPAD])(hsm + HSTAGES * 128 * HPAD);

    int tid = threadIdx.x;
    int lane = tid & 31;
    int wid = tid >> 5;
    int wr = wid >> 2;
    int wc = wid & 3;
    int grp = lane >> 2;
    int qid = lane & 3;
    int bm = blockIdx.x * 128;
    int bn = blockIdx.y * 128;

    float acc[4][4][4];
#pragma unroll
    for (int i = 0; i < 4; i++)
#pragma unroll
        for (int j = 0; j < 4; j++)
#pragma unroll
            for (int r = 0; r < 4; r++) acc[i][j][r] = 0.f;

    int r0i = tid >> 2,          c0i = (tid & 3) * 8;
    int r1i = (tid + 256) >> 2,  c1i = (tid & 3) * 8;
    int a_g0 = bm + r0i; if (a_g0 >= M) a_g0 = M - 1;
    int a_g1 = bm + r1i; if (a_g1 >= M) a_g1 = M - 1;
    int b_g0 = bn + r0i, b_g1 = bn + r1i;

    int a_lrow = wr * 64 + (lane & 15);
    int a_lk   = 8 * (lane >> 4);
    int b_lcol = wc * 32 + (lane & 7);
    int b_lk   = 8 * ((lane >> 3) & 1);

    const int KT = K / 32;

#define PREFETCH(st, kt_) do { \
        int kb_ = (kt_) * 32; \
        cpasync16(&As[st][r0i][c0i], A + (long)a_g0 * K + kb_ + c0i); \
        cpasync16(&As[st][r1i][c1i], A + (long)a_g1 * K + kb_ + c1i); \
        cpasync16(&Bs[st][r0i][c0i], Bt + (long)b_g0 * K + kb_ + c0i); \
        cpasync16(&Bs[st][r1i][c1i], Bt + (long)b_g1 * K + kb_ + c1i); \
        asm volatile("cp.async.commit_group;"); \
    } while (0)

    for (int st = 0; st < 3 && st < KT; st++) PREFETCH(st, st);

    for (int kt = 0; kt < KT; kt++) {
        int rem = KT - 1 - kt;
        if (rem >= 2)      asm volatile("cp.async.wait_group 2;");
        else if (rem == 1) asm volatile("cp.async.wait_group 1;");
        else               asm volatile("cp.async.wait_group 0;");
        __syncthreads();
        if (kt + 3 < KT) PREFETCH((kt + 3) & 3, kt + 3);
        int buf = kt & 3;

        uint32_t asb = (uint32_t)__cvta_generic_to_shared(&As[buf][0][0]);
        uint32_t bsb = (uint32_t)__cvta_generic_to_shared(&Bs[buf][0][0]);

#pragma unroll
        for (int ks = 0; ks < 32; ks += 16) {
            unsigned afr[4][4];
#pragma unroll
            for (int mi = 0; mi < 4; mi++)
                ldsm_x4(afr[mi], asb + ((a_lrow + mi * 16) * HPAD + ks + a_lk) * 2);
            unsigned bfr[4][2];
#pragma unroll
            for (int ni = 0; ni < 4; ni++)
                ldsm_x2(bfr[ni], bsb + ((b_lcol + ni * 8) * HPAD + ks + b_lk) * 2);
#pragma unroll
            for (int mi = 0; mi < 4; mi++)
#pragma unroll
                for (int ni = 0; ni < 4; ni++)
                    mma_f16(acc[mi][ni], afr[mi], bfr[ni]);
        }
        __syncthreads();
    }
#undef PREFETCH

#pragma unroll
    for (int mi = 0; mi < 4; mi++) {
        int r0 = bm + wr * 64 + mi * 16 + grp;
#pragma unroll
        for (int ni = 0; ni < 4; ni++) {
            int gc = bn + wc * 32 + ni * 8 + 2 * qid;
            float bz0 = bias[gc], bz1 = bias[gc + 1];
            if (halfOut) {
                __half* Oh = (__half*)Ov;
                if (r0 < M)
                    *(__half2*)&Oh[(long)r0 * NTOT + gc] =
                        __floats2half2_rn(acc[mi][ni][0] + bz0, acc[mi][ni][1] + bz1);
                if (r0 + 8 < M)
                    *(__half2*)&Oh[(long)(r0 + 8) * NTOT + gc] =
                        __floats2half2_rn(acc[mi][ni][2] + bz0, acc[mi][ni][3] + bz1);
            } else {
                float* Of = (float*)Ov;
                if (r0 < M) {
                    Of[(long)r0 * NTOT + gc]     = acc[mi][ni][0] + bz0;
                    Of[(long)r0 * NTOT + gc + 1] = acc[mi][ni][1] + bz1;
                }
                if (r0 + 8 < M) {
                    Of[(long)(r0 + 8) * NTOT + gc]     = acc[mi][ni][2] + bz0;
                    Of[(long)(r0 + 8) * NTOT + gc + 1] = acc[mi][ni][3] + bz1;
                }
            }
        }
    }
}

// ---------------- fused edge kernel: scores + softmax + aggregate + LN stats ----------------
template <int D, int WARPS, int MAXE>
__global__ void __launch_bounds__(WARPS * 32)
edge_fused_kernel(const __half* __restrict__ q, const __half* __restrict__ k,
                  const __half* __restrict__ v, const float* __restrict__ skip,
                  float* __restrict__ out, float* __restrict__ buck, float scale) {
    int n = blockIdx.x;
    __shared__ __half2 qs[D / 2];
    __shared__ float wsh[MAXE];
    __shared__ int   ssh[MAXE];
    __shared__ float red[WARPS], red2[WARPS];
    __shared__ float bc_m, bc_inv;
    int tid = threadIdx.x, lane = tid & 31, wid = tid >> 5;
    int s0 = g_off[n], s1 = g_off[n + 1], deg = s1 - s0;

    const __half2* q2 = (const __half2*)(q + (long)n * D);
    for (int i = tid; i < D / 2; i += WARPS * 32) qs[i] = q2[i];
    __syncthreads();

    float lmax = -3.4e38f;
    for (int j = s0 + wid; j < s1; j += WARPS) {
        int src = g_csrsrc[j];
        const __half2* kr = (const __half2*)(k + (long)src * D);
        float acc = 0.f;
#pragma unroll
        for (int i = 0; i < D / 64; i++) {
            float2 a = __half22float2(qs[lane + 32 * i]);
            float2 b = __half22float2(kr[lane + 32 * i]);
            acc += a.x * b.x + a.y * b.y;
        }
#pragma unroll
        for (int o = 16; o > 0; o >>= 1) acc += __shfl_xor_sync(0xffffffffu, acc, o);
        float sc = acc * scale;
        int loc = j - s0;
        if (lane == 0) {
            if (loc < MAXE) { wsh[loc] = sc; ssh[loc] = src; }
            else            g_w[j] = sc;
        }
        lmax = fmaxf(lmax, sc);
    }
    if (lane == 0) red[wid] = lmax;
    __syncthreads();
    if (tid == 0) {
        float m = red[0];
#pragma unroll
        for (int i = 1; i < WARPS; i++) m = fmaxf(m, red[i]);
        bc_m = m;
    }
    __syncthreads();
    float m = bc_m;

    float lsum = 0.f;
    for (int loc = tid; loc < deg; loc += WARPS * 32) {
        float sc = (loc < MAXE) ? wsh[loc] : g_w[s0 + loc];
        float w = __expf(sc - m);
        if (loc < MAXE) wsh[loc] = w; else g_w[s0 + loc] = w;
        lsum += w;
    }
#pragma unroll
    for (int o = 16; o > 0; o >>= 1) lsum += __shfl_xor_sync(0xffffffffu, lsum, o);
    if (lane == 0) red[wid] = lsum;
    __syncthreads();
    if (tid == 0) {
        float sum = 0.f;
#pragma unroll
        for (int i = 0; i < WARPS; i++) sum += red[i];
        bc_inv = (sum > 0.f) ? 1.f / sum : 0.f;
    }
    __syncthreads();
    float inv = bc_inv;

    float sloc = 0.f, s2loc = 0.f;
    if (tid < D / 2) {
        float ax = 0.f, ay = 0.f;
        const __half2* v2 = (const __half2*)v;
        for (int loc = 0; loc < deg; loc++) {
            int src  = (loc < MAXE) ? ssh[loc] : g_csrsrc[s0 + loc];
            float we = (loc < MAXE) ? wsh[loc] : g_w[s0 + loc];
            float2 vv = __half22float2(v2[(long)src * (D / 2) + tid]);
            ax += we * vv.x;
            ay += we * vv.y;
        }
        long base = (long)n * D + 2 * tid;
        float h0 = skip[base]     + ax * inv;
        float h1 = skip[base + 1] + ay * inv;
        out[base]     = h0;
        out[base + 1] = h1;
        sloc  = h0 + h1;
        s2loc = h0 * h0 + h1 * h1;
    }
#pragma unroll
    for (int o = 16; o > 0; o >>= 1) {
        sloc  += __shfl_xor_sync(0xffffffffu, sloc, o);
        s2loc += __shfl_xor_sync(0xffffffffu, s2loc, o);
    }
    if (lane == 0) { red[wid] = sloc; red2[wid] = s2loc; }
    __syncthreads();
    if (tid == 0) {
        float ts = 0.f, ts2 = 0.f;
#pragma unroll
        for (int i = 0; i < WARPS; i++) { ts += red[i]; ts2 += red2[i]; }
        int b = (n & 63) * 2;
        atomicAdd(&buck[b], ts);
        atomicAdd(&buck[b + 1], ts2);
    }
}

// ---------------- normalize (stats computed in-block from buckets) ----------------
__device__ __forceinline__ void block_stats(const float* __restrict__ buck, float M,
                                            float& fm, float& inv) {
    __shared__ float sh[2];
    if (threadIdx.x < 32) {
        int l = threadIdx.x;
        float s  = buck[2 * l]     + buck[2 * (l + 32)];
        float s2 = buck[2 * l + 1] + buck[2 * (l + 32) + 1];
#pragma unroll
        for (int o = 16; o > 0; o >>= 1) {
            s  += __shfl_xor_sync(0xffffffffu, s, o);
            s2 += __shfl_xor_sync(0xffffffffu, s2, o);
        }
        if (l == 0) {
            float mean = s / M;
            float var = s2 / M - mean * mean;
            if (var < 0.f) var = 0.f;
            sh[0] = mean;
            sh[1] = 1.0f / (sqrtf(var) + 1e-5f);
        }
    }
    __syncthreads();
    fm = sh[0];
    inv = sh[1];
}

__global__ void normalize_elu_h_kernel(const float* __restrict__ h,
                                       const float* __restrict__ gamma,
                                       const float* __restrict__ beta,
                                       __half* __restrict__ out,
                                       const float* __restrict__ buck,
                                       int dmask, long M) {
    float fm, inv;
    block_stats(buck, (float)M, fm, inv);
    long stride = (long)gridDim.x * blockDim.x;
    for (long i = (long)blockIdx.x * blockDim.x + threadIdx.x; i < M; i += stride) {
        int c = (int)(i & dmask);
        float y = (h[i] - fm) * inv * gamma[c] + beta[c];
        y = (y > 0.f) ? y : expm1f(y);
        out[i] = __float2half(y);
    }
}

__global__ void normalize_f_kernel(const float* __restrict__ h,
                                   const float* __restrict__ gamma,
                                   const float* __restrict__ beta,
                                   float* __restrict__ out,
                                   const float* __restrict__ buck,
                                   int dmask, long M) {
    float fm, inv;
    block_stats(buck, (float)M, fm, inv);
    long stride = (long)gridDim.x * blockDim.x;
    for (long i = (long)blockIdx.x * blockDim.x + threadIdx.x; i < M; i += stride) {
        int c = (int)(i & dmask);
        out[i] = (h[i] - fm) * inv * gamma[c] + beta[c];
    }
}

// ---------------- host launcher ----------------
extern "C" void kernel_launch(void* const* d_in, const int* in_sizes, int n_in,
                              void* d_out, int out_size) {
    const float* x    = (const float*)d_in[0];
    const float* Wq1  = (const float*)d_in[1];
    const float* bq1  = (const float*)d_in[2];
    const float* Wk1  = (const float*)d_in[3];
    const float* bk1  = (const float*)d_in[4];
    const float* Wv1  = (const float*)d_in[5];
    const float* bv1  = (const float*)d_in[6];
    const float* Ws1  = (const float*)d_in[7];
    const float* bs1  = (const float*)d_in[8];
    const float* ga1  = (const float*)d_in[9];
    const float* be1  = (const float*)d_in[10];
    const float* Wq2  = (const float*)d_in[11];
    const float* bq2  = (const float*)d_in[12];
    const float* Wk2  = (const float*)d_in[13];
    const float* bk2  = (const float*)d_in[14];
    const float* Wv2  = (const float*)d_in[15];
    const float* bv2  = (const float*)d_in[16];
    const float* Ws2  = (const float*)d_in[17];
    const float* bs2  = (const float*)d_in[18];
    const float* ga2  = (const float*)d_in[19];
    const float* be2  = (const float*)d_in[20];
    const void*  ei   = d_in[21];
    float* out = (float*)d_out;

    void *p_qh, *p_kh, *p_vh, *p_s, *p_h, *p_xch, *p_wch, *p_wch2, *p_deg, *p_buck, *p_is64;
    cudaGetSymbolAddress(&p_qh, g_qh);
    cudaGetSymbolAddress(&p_kh, g_kh);
    cudaGetSymbolAddress(&p_vh, g_vh);
    cudaGetSymbolAddress(&p_s, g_s);
    cudaGetSymbolAddress(&p_h, g_h);
    cudaGetSymbolAddress(&p_xch, g_xch);
    cudaGetSymbolAddress(&p_wch, g_wch);
    cudaGetSymbolAddress(&p_wch2, g_wch2);
    cudaGetSymbolAddress(&p_deg, g_deg);
    cudaGetSymbolAddress(&p_buck, g_buck);
    cudaGetSymbolAddress(&p_is64, g_is64);

    __half* qh  = (__half*)p_qh;
    __half* kh  = (__half*)p_kh;
    __half* vh  = (__half*)p_vh;
    float*  s   = (float*)p_s;
    float*  h   = (float*)p_h;
    __half* xh  = (__half*)p_xch;
    __half* wh  = (__half*)p_wch;
    __half* wh2 = (__half*)p_wch2;
    float*  bkk = (float*)p_buck;

    cudaFuncSetAttribute(gemm4_f16_n256_kernel<IN_DIM>,
                         cudaFuncAttributeMaxDynamicSharedMemorySize, GEMM256_SMEM_BYTES);
    cudaFuncSetAttribute(gemm4_f16_kernel<OUT_DIM, HID>,
                         cudaFuncAttributeMaxDynamicSharedMemorySize, GEMM_SMEM_BYTES);

    // ---- side stream: x convert, then CSR build (both independent of weights) ----
    cudaStream_t s2;
    cudaStreamCreateWithFlags(&s2, cudaStreamNonBlocking);
    cudaEvent_t evFork, evX, evJoin;
    cudaEventCreateWithFlags(&evFork, cudaEventDisableTiming);
    cudaEventCreateWithFlags(&evX, cudaEventDisableTiming);
    cudaEventCreateWithFlags(&evJoin, cudaEventDisableTiming);

    cudaEventRecord(evFork, 0);
    cudaStreamWaitEvent(s2, evFork, 0);

    cvt_f2h_kernel<<<2048, 256, 0, s2>>>(x, xh, N_NODES * IN_DIM);
    cudaEventRecord(evX, s2);
    cudaMemsetAsync(p_is64, 0xFF, sizeof(int), s2);
    detect_idx_kernel<<<1024, 256, 0, s2>>>((const long long*)ei);
    cudaMemsetAsync(p_deg, 0, N_NODES * sizeof(int), s2);
    cvt_count_kernel<<<2048, 256, 0, s2>>>(ei);
    scan_offsets_kernel<<<1, 1024, 0, s2>>>();
    fill_csr_kernel<<<2048, 256, 0, s2>>>();
    cudaEventRecord(evJoin, s2);

    // main stream: weight converts (parallel with x convert), then layer-1 GEMM
    cudaMemsetAsync(p_buck, 0, 256 * sizeof(float), 0);
    {
        dim3 g(256, 4);
        cvtT4_f2h_kernel<<<g, 256>>>(Wq1, Wk1, Wv1, Ws1, wh, IN_DIM, HID);
    }
    {
        dim3 g(128, 4);
        cvtT4_f2h_kernel<<<g, 256>>>(Wq2, Wk2, Wv2, Ws2, wh2, HID, OUT_DIM);
    }
    cudaStreamWaitEvent(0, evX, 0);
    {
        dim3 grid((N_NODES + 127) / 128, 1, 4);
        gemm4_f16_n256_kernel<IN_DIM><<<grid, 256, GEMM256_SMEM_BYTES>>>(
            xh, wh, bq1, bk1, bv1, bs1, qh, kh, vh, s, N_NODES);
    }

    cudaStreamWaitEvent(0, evJoin, 0);

    edge_fused_kernel<HID, 8, 64><<<N_NODES, 256>>>(qh, kh, vh, s, h, bkk, 1.0f / 16.0f);
    normalize_elu_h_kernel<<<2048, 256>>>(h, ga1, be1, xh, bkk, HID - 1, (long)N_NODES * HID);

    // ---- layer 2 ----
    {
        dim3 grid((N_NODES + 127) / 128, OUT_DIM / 128, 4);
        gemm4_f16_kernel<OUT_DIM, HID><<<grid, 256, GEMM_SMEM_BYTES>>>(
            xh, wh2, bq2, bk2, bv2, bs2, qh, kh, vh, s, N_NODES);
    }
    edge_fused_kernel<OUT_DIM, 4, 64><<<N_NODES, 128>>>(qh, kh, vh, s, h, bkk + 128,
                                                        0.08838834764831845f);
    normalize_f_kernel<<<2048, 256>>>(h, ga2, be2, out, bkk + 128, OUT_DIM - 1,
                                      (long)N_NODES * OUT_DIM);

    cudaEventDestroy(evFork);
    cudaEventDestroy(evX);
    cudaEventDestroy(evJoin);
    cudaStreamDestroy(s2);
}

// round 16
// speedup vs baseline: 1.0159x; 1.0159x over previous
#include <cuda_runtime.h>
#include <cuda_fp16.h>
#include <math.h>
#include <stdint.h>

#define N_NODES 50000
#define N_EDGES 800000
#define IN_DIM  512
#define HID     256
#define OUT_DIM 128

// ---------------- scratch (static device globals; no allocation) ----------------
__device__ __half   g_qh[N_NODES * HID];
__device__ __half   g_kh[N_NODES * HID];
__device__ __half   g_vh[N_NODES * HID];
__device__ float    g_s[N_NODES * HID];
__device__ float    g_h[N_NODES * HID];
__device__ __half   g_xch[N_NODES * IN_DIM];
__device__ __half   g_wch[4 * IN_DIM * HID];
__device__ __half   g_wch2[4 * HID * OUT_DIM];
__device__ float    g_w[N_EDGES];
__device__ int      g_deg[N_NODES];
__device__ int      g_off[N_NODES + 1];
__device__ int      g_cursor[N_NODES];
__device__ int      g_csrsrc[N_EDGES];
__device__ int      g_src[N_EDGES];
__device__ int      g_dst[N_EDGES];
__device__ float    g_buck[256];
__device__ int      g_is64;

// ---------------- edge-index dtype detection ----------------
__global__ void detect_idx_kernel(const long long* __restrict__ ei) {
    int stride = gridDim.x * blockDim.x;
    int bad = 0;
    for (int i = blockIdx.x * blockDim.x + threadIdx.x; i < N_EDGES; i += stride) {
        long long v = ei[i];
        if (v < 0 || v >= N_NODES) bad = 1;
    }
    if (__syncthreads_or(bad) && threadIdx.x == 0) atomicAnd(&g_is64, 0);
}

__global__ void cvt_count_kernel(const void* __restrict__ eiv) {
    const bool is64 = (g_is64 != 0);
    const long long* e64 = (const long long*)eiv;
    const int*       e32 = (const int*)eiv;
    int stride = gridDim.x * blockDim.x;
    for (int e = blockIdx.x * blockDim.x + threadIdx.x; e < N_EDGES; e += stride) {
        long long sv = is64 ? e64[e]           : (long long)e32[e];
        long long dv = is64 ? e64[N_EDGES + e] : (long long)e32[N_EDGES + e];
        int s = (int)sv, d = (int)dv;
        if (s < 0) s = 0; if (s >= N_NODES) s = N_NODES - 1;
        if (d < 0) d = 0; if (d >= N_NODES) d = N_NODES - 1;
        g_src[e] = s;
        g_dst[e] = d;
        atomicAdd(&g_deg[d], 1);
    }
}

__global__ void scan_offsets_kernel() {
    __shared__ int partial[1024];
    int t = threadIdx.x;
    const int C = (N_NODES + 1023) / 1024;
    int lo = t * C;
    int hi = lo + C; if (hi > N_NODES) hi = N_NODES;
    if (lo > N_NODES) lo = N_NODES;
    int s = 0;
    for (int i = lo; i < hi; i++) s += g_deg[i];
    partial[t] = s;
    __syncthreads();
    for (int o = 1; o < 1024; o <<= 1) {
        int add = (t >= o) ? partial[t - o] : 0;
        __syncthreads();
        partial[t] += add;
        __syncthreads();
    }
    int run = partial[t] - s;
    for (int i = lo; i < hi; i++) {
        g_off[i] = run;
        g_cursor[i] = run;
        run += g_deg[i];
    }
    if (t == 1023) g_off[N_NODES] = partial[1023];
}

__global__ void fill_csr_kernel() {
    int stride = gridDim.x * blockDim.x;
    for (int e = blockIdx.x * blockDim.x + threadIdx.x; e < N_EDGES; e += stride) {
        int p = atomicAdd(&g_cursor[g_dst[e]], 1);
        if (p >= 0 && p < N_EDGES) g_csrsrc[p] = g_src[e];
    }
}

// ---------------- fp16 pre-conversion ----------------
__global__ void cvt_f2h_kernel(const float* __restrict__ in, __half* __restrict__ out, int n) {
    int stride = gridDim.x * blockDim.x;
    for (int i = blockIdx.x * blockDim.x + threadIdx.x; i < n; i += stride)
        out[i] = __float2half(in[i]);
}

__global__ void cvtT4_f2h_kernel(const float* __restrict__ W0, const float* __restrict__ W1,
                                 const float* __restrict__ W2, const float* __restrict__ W3,
                                 __half* __restrict__ out, int K, int N) {
    const float* W;
    switch (blockIdx.y) {
        case 0: W = W0; break;
        case 1: W = W1; break;
        case 2: W = W2; break;
        default: W = W3; break;
    }
    __half* o = out + (long)blockIdx.y * K * N;
    int stride = gridDim.x * blockDim.x;
    int total = K * N;
    for (int i = blockIdx.x * blockDim.x + threadIdx.x; i < total; i += stride) {
        int k = i / N, n = i - k * N;
        o[n * K + k] = __float2half(W[i]);
    }
}

// ---------------- common MMA helpers ----------------
__device__ __forceinline__ void mma_f16(float* c, const unsigned* a, const unsigned* b) {
    asm volatile(
        "mma.sync.aligned.m16n8k16.row.col.f32.f16.f16.f32 "
        "{%0,%1,%2,%3}, {%4,%5,%6,%7}, {%8,%9}, {%0,%1,%2,%3};"
        : "+f"(c[0]), "+f"(c[1]), "+f"(c[2]), "+f"(c[3])
        : "r"(a[0]), "r"(a[1]), "r"(a[2]), "r"(a[3]), "r"(b[0]), "r"(b[1]));
}

__device__ __forceinline__ void ldsm_x4(unsigned* r, uint32_t saddr) {
    asm volatile("ldmatrix.sync.aligned.m8n8.x4.shared.b16 {%0,%1,%2,%3}, [%4];"
        : "=r"(r[0]), "=r"(r[1]), "=r"(r[2]), "=r"(r[3]) : "r"(saddr));
}

__device__ __forceinline__ void ldsm_x2(unsigned* r, uint32_t saddr) {
    asm volatile("ldmatrix.sync.aligned.m8n8.x2.shared.b16 {%0,%1}, [%2];"
        : "=r"(r[0]), "=r"(r[1]) : "r"(saddr));
}

__device__ __forceinline__ void cpasync16(void* smem, const void* gmem) {
    unsigned saddr = (unsigned)__cvta_generic_to_shared(smem);
    asm volatile("cp.async.ca.shared.global [%0], [%1], 16;" :: "r"(saddr), "l"(gmem));
}

#define HPAD 40
#define HSTAGES 4
#define GEMM_SMEM_BYTES (HSTAGES * 2 * 128 * HPAD * 2)

// ---------------- GEMM: 128x128 block tile (proven R13 config) ----------------
template <int NTOT, int K>
__global__ void __launch_bounds__(256, 2)
gemm4_f16_kernel(const __half* __restrict__ A, const __half* __restrict__ BtAll,
                 const float* __restrict__ c0, const float* __restrict__ c1,
                 const float* __restrict__ c2, const float* __restrict__ c3,
                 void* __restrict__ O0, void* __restrict__ O1,
                 void* __restrict__ O2, void* __restrict__ O3, int M) {
    const float* bias; void* Ov;
    switch (blockIdx.z) {
        case 0: bias = c0; Ov = O0; break;
        case 1: bias = c1; Ov = O1; break;
        case 2: bias = c2; Ov = O2; break;
        default: bias = c3; Ov = O3; break;
    }
    const bool halfOut = (blockIdx.z < 3);
    const __half* Bt = BtAll + (long)blockIdx.z * NTOT * K;

    extern __shared__ __half hsm[];
    __half (*As)[128][HPAD] = (__half(*)[128][HPAD])hsm;
    __half (*Bs)[128][HPAD] = (__half(*)[128][HPAD])(hsm + HSTAGES * 128 * HPAD);

    int tid = threadIdx.x;
    int lane = tid & 31;
    int wid = tid >> 5;
    int wr = wid >> 2;
    int wc = wid & 3;
    int grp = lane >> 2;
    int qid = lane & 3;
    int bm = blockIdx.x * 128;
    int bn = blockIdx.y * 128;

    float acc[4][4][4];
#pragma unroll
    for (int i = 0; i < 4; i++)
#pragma unroll
        for (int j = 0; j < 4; j++)
#pragma unroll
            for (int r = 0; r < 4; r++) acc[i][j][r] = 0.f;

    int r0i = tid >> 2,          c0i = (tid & 3) * 8;
    int r1i = (tid + 256) >> 2,  c1i = (tid & 3) * 8;
    int a_g0 = bm + r0i; if (a_g0 >= M) a_g0 = M - 1;
    int a_g1 = bm + r1i; if (a_g1 >= M) a_g1 = M - 1;
    int b_g0 = bn + r0i, b_g1 = bn + r1i;

    int a_lrow = wr * 64 + (lane & 15);
    int a_lk   = 8 * (lane >> 4);
    int b_lcol = wc * 32 + (lane & 7);
    int b_lk   = 8 * ((lane >> 3) & 1);

    const int KT = K / 32;

#define PREFETCH(st, kt_) do { \
        int kb_ = (kt_) * 32; \
        cpasync16(&As[st][r0i][c0i], A + (long)a_g0 * K + kb_ + c0i); \
        cpasync16(&As[st][r1i][c1i], A + (long)a_g1 * K + kb_ + c1i); \
        cpasync16(&Bs[st][r0i][c0i], Bt + (long)b_g0 * K + kb_ + c0i); \
        cpasync16(&Bs[st][r1i][c1i], Bt + (long)b_g1 * K + kb_ + c1i); \
        asm volatile("cp.async.commit_group;"); \
    } while (0)

    for (int st = 0; st < 3 && st < KT; st++) PREFETCH(st, st);

    for (int kt = 0; kt < KT; kt++) {
        int rem = KT - 1 - kt;
        if (rem >= 2)      asm volatile("cp.async.wait_group 2;");
        else if (rem == 1) asm volatile("cp.async.wait_group 1;");
        else               asm volatile("cp.async.wait_group 0;");
        __syncthreads();
        if (kt + 3 < KT) PREFETCH((kt + 3) & 3, kt + 3);
        int buf = kt & 3;

        uint32_t asb = (uint32_t)__cvta_generic_to_shared(&As[buf][0][0]);
        uint32_t bsb = (uint32_t)__cvta_generic_to_shared(&Bs[buf][0][0]);

#pragma unroll
        for (int ks = 0; ks < 32; ks += 16) {
            unsigned afr[4][4];
#pragma unroll
            for (int mi = 0; mi < 4; mi++)
                ldsm_x4(afr[mi], asb + ((a_lrow + mi * 16) * HPAD + ks + a_lk) * 2);
            unsigned bfr[4][2];
#pragma unroll
            for (int ni = 0; ni < 4; ni++)
                ldsm_x2(bfr[ni], bsb + ((b_lcol + ni * 8) * HPAD + ks + b_lk) * 2);
#pragma unroll
            for (int mi = 0; mi < 4; mi++)
#pragma unroll
                for (int ni = 0; ni < 4; ni++)
                    mma_f16(acc[mi][ni], afr[mi], bfr[ni]);
        }
        __syncthreads();
    }
#undef PREFETCH

#pragma unroll
    for (int mi = 0; mi < 4; mi++) {
        int r0 = bm + wr * 64 + mi * 16 + grp;
#pragma unroll
        for (int ni = 0; ni < 4; ni++) {
            int gc = bn + wc * 32 + ni * 8 + 2 * qid;
            float bz0 = bias[gc], bz1 = bias[gc + 1];
            if (halfOut) {
                __half* Oh = (__half*)Ov;
                if (r0 < M)
                    *(__half2*)&Oh[(long)r0 * NTOT + gc] =
                        __floats2half2_rn(acc[mi][ni][0] + bz0, acc[mi][ni][1] + bz1);
                if (r0 + 8 < M)
                    *(__half2*)&Oh[(long)(r0 + 8) * NTOT + gc] =
                        __floats2half2_rn(acc[mi][ni][2] + bz0, acc[mi][ni][3] + bz1);
            } else {
                float* Of = (float*)Ov;
                if (r0 < M) {
                    Of[(long)r0 * NTOT + gc]     = acc[mi][ni][0] + bz0;
                    Of[(long)r0 * NTOT + gc + 1] = acc[mi][ni][1] + bz1;
                }
                if (r0 + 8 < M) {
                    Of[(long)(r0 + 8) * NTOT + gc]     = acc[mi][ni][2] + bz0;
                    Of[(long)(r0 + 8) * NTOT + gc + 1] = acc[mi][ni][3] + bz1;
                }
            }
        }
    }
}

// ---------------- fused edge kernel: scores + softmax + split aggregate + LN stats ----------
// Block = max(WARPS*32, D) threads. Phase C: thread pairs (c, c+D/2 threads) split
// even/odd edges per channel; partner partials combine via smem.
template <int D, int WARPS, int MAXE>
__global__ void __launch_bounds__(WARPS * 32)
edge_fused_kernel(const __half* __restrict__ q, const __half* __restrict__ k,
                  const __half* __restrict__ v, const float* __restrict__ skip,
                  float* __restrict__ out, float* __restrict__ buck, float scale) {
    int n = blockIdx.x;
    __shared__ __half2 qs[D / 2];
    __shared__ float wsh[MAXE];
    __shared__ int   ssh[MAXE];
    __shared__ float2 part[D / 2];
    __shared__ float red[WARPS], red2[WARPS];
    __shared__ float bc_m, bc_inv;
    int tid = threadIdx.x, lane = tid & 31, wid = tid >> 5;
    int s0 = g_off[n], s1 = g_off[n + 1], deg = s1 - s0;

    const __half2* q2 = (const __half2*)(q + (long)n * D);
    for (int i = tid; i < D / 2; i += WARPS * 32) qs[i] = q2[i];
    __syncthreads();

    // phase A: scores (warp per edge)
    float lmax = -3.4e38f;
    for (int j = s0 + wid; j < s1; j += WARPS) {
        int src = g_csrsrc[j];
        const __half2* kr = (const __half2*)(k + (long)src * D);
        float acc = 0.f;
#pragma unroll
        for (int i = 0; i < D / 64; i++) {
            float2 a = __half22float2(qs[lane + 32 * i]);
            float2 b = __half22float2(kr[lane + 32 * i]);
            acc += a.x * b.x + a.y * b.y;
        }
#pragma unroll
        for (int o = 16; o > 0; o >>= 1) acc += __shfl_xor_sync(0xffffffffu, acc, o);
        float sc = acc * scale;
        int loc = j - s0;
        if (lane == 0) {
            if (loc < MAXE) { wsh[loc] = sc; ssh[loc] = src; }
            else            g_w[j] = sc;
        }
        lmax = fmaxf(lmax, sc);
    }
    if (lane == 0) red[wid] = lmax;
    __syncthreads();
    if (tid == 0) {
        float m = red[0];
#pragma unroll
        for (int i = 1; i < WARPS; i++) m = fmaxf(m, red[i]);
        bc_m = m;
    }
    __syncthreads();
    float m = bc_m;

    // phase B: exp + sum
    float lsum = 0.f;
    for (int loc = tid; loc < deg; loc += WARPS * 32) {
        float sc = (loc < MAXE) ? wsh[loc] : g_w[s0 + loc];
        float w = __expf(sc - m);
        if (loc < MAXE) wsh[loc] = w; else g_w[s0 + loc] = w;
        lsum += w;
    }
#pragma unroll
    for (int o = 16; o > 0; o >>= 1) lsum += __shfl_xor_sync(0xffffffffu, lsum, o);
    if (lane == 0) red[wid] = lsum;
    __syncthreads();
    if (tid == 0) {
        float sum = 0.f;
#pragma unroll
        for (int i = 0; i < WARPS; i++) sum += red[i];
        bc_inv = (sum > 0.f) ? 1.f / sum : 0.f;
    }
    __syncthreads();
    float inv = bc_inv;

    // phase C: split aggregation. Threads [0, D/2): even edges; [D/2, D): odd edges.
    {
        int c2 = tid & (D / 2 - 1);
        int halfsel = (tid < D / 2) ? 0 : 1;
        bool active = (tid < D);
        float ax = 0.f, ay = 0.f;
        if (active) {
            const __half2* v2 = (const __half2*)v;
            for (int loc = halfsel; loc < deg; loc += 2) {
                int src  = (loc < MAXE) ? ssh[loc] : g_csrsrc[s0 + loc];
                float we = (loc < MAXE) ? wsh[loc] : g_w[s0 + loc];
                float2 vv = __half22float2(v2[(long)src * (D / 2) + c2]);
                ax += we * vv.x;
                ay += we * vv.y;
            }
            if (halfsel) part[c2] = make_float2(ax, ay);
        }
        __syncthreads();
        float sloc = 0.f, s2loc = 0.f;
        if (active && !halfsel) {
            float2 p = part[c2];
            ax += p.x; ay += p.y;
            long base = (long)n * D + 2 * c2;
            float h0 = skip[base]     + ax * inv;
            float h1 = skip[base + 1] + ay * inv;
            out[base]     = h0;
            out[base + 1] = h1;
            sloc  = h0 + h1;
            s2loc = h0 * h0 + h1 * h1;
        }
#pragma unroll
        for (int o = 16; o > 0; o >>= 1) {
            sloc  += __shfl_xor_sync(0xffffffffu, sloc, o);
            s2loc += __shfl_xor_sync(0xffffffffu, s2loc, o);
        }
        if (lane == 0) { red[wid] = sloc; red2[wid] = s2loc; }
    }
    __syncthreads();
    if (tid == 0) {
        float ts = 0.f, ts2 = 0.f;
#pragma unroll
        for (int i = 0; i < WARPS; i++) { ts += red[i]; ts2 += red2[i]; }
        int b = (n & 63) * 2;
        atomicAdd(&buck[b], ts);
        atomicAdd(&buck[b + 1], ts2);
    }
}

// ---------------- normalize (stats computed in-block from buckets) ----------------
__device__ __forceinline__ void block_stats(const float* __restrict__ buck, float M,
                                            float& fm, float& inv) {
    __shared__ float sh[2];
    if (threadIdx.x < 32) {
        int l = threadIdx.x;
        float s  = buck[2 * l]     + buck[2 * (l + 32)];
        float s2 = buck[2 * l + 1] + buck[2 * (l + 32) + 1];
#pragma unroll
        for (int o = 16; o > 0; o >>= 1) {
            s  += __shfl_xor_sync(0xffffffffu, s, o);
            s2 += __shfl_xor_sync(0xffffffffu, s2, o);
        }
        if (l == 0) {
            float mean = s / M;
            float var = s2 / M - mean * mean;
            if (var < 0.f) var = 0.f;
            sh[0] = mean;
            sh[1] = 1.0f / (sqrtf(var) + 1e-5f);
        }
    }
    __syncthreads();
    fm = sh[0];
    inv = sh[1];
}

__global__ void normalize_elu_h_kernel(const float* __restrict__ h,
                                       const float* __restrict__ gamma,
                                       const float* __restrict__ beta,
                                       __half* __restrict__ out,
                                       const float* __restrict__ buck,
                                       int dmask, long M) {
    float fm, inv;
    block_stats(buck, (float)M, fm, inv);
    long stride = (long)gridDim.x * blockDim.x;
    for (long i = (long)blockIdx.x * blockDim.x + threadIdx.x; i < M; i += stride) {
        int c = (int)(i & dmask);
        float y = (h[i] - fm) * inv * gamma[c] + beta[c];
        y = (y > 0.f) ? y : expm1f(y);
        out[i] = __float2half(y);
    }
}

__global__ void normalize_f_kernel(const float* __restrict__ h,
                                   const float* __restrict__ gamma,
                                   const float* __restrict__ beta,
                                   float* __restrict__ out,
                                   const float* __restrict__ buck,
                                   int dmask, long M) {
    float fm, inv;
    block_stats(buck, (float)M, fm, inv);
    long stride = (long)gridDim.x * blockDim.x;
    for (long i = (long)blockIdx.x * blockDim.x + threadIdx.x; i < M; i += stride) {
        int c = (int)(i & dmask);
        out[i] = (h[i] - fm) * inv * gamma[c] + beta[c];
    }
}

// ---------------- host launcher ----------------
extern "C" void kernel_launch(void* const* d_in, const int* in_sizes, int n_in,
                              void* d_out, int out_size) {
    const float* x    = (const float*)d_in[0];
    const float* Wq1  = (const float*)d_in[1];
    const float* bq1  = (const float*)d_in[2];
    const float* Wk1  = (const float*)d_in[3];
    const float* bk1  = (const float*)d_in[4];
    const float* Wv1  = (const float*)d_in[5];
    const float* bv1  = (const float*)d_in[6];
    const float* Ws1  = (const float*)d_in[7];
    const float* bs1  = (const float*)d_in[8];
    const float* ga1  = (const float*)d_in[9];
    const float* be1  = (const float*)d_in[10];
    const float* Wq2  = (const float*)d_in[11];
    const float* bq2  = (const float*)d_in[12];
    const float* Wk2  = (const float*)d_in[13];
    const float* bk2  = (const float*)d_in[14];
    const float* Wv2  = (const float*)d_in[15];
    const float* bv2  = (const float*)d_in[16];
    const float* Ws2  = (const float*)d_in[17];
    const float* bs2  = (const float*)d_in[18];
    const float* ga2  = (const float*)d_in[19];
    const float* be2  = (const float*)d_in[20];
    const void*  ei   = d_in[21];
    float* out = (float*)d_out;

    void *p_qh, *p_kh, *p_vh, *p_s, *p_h, *p_xch, *p_wch, *p_wch2, *p_deg, *p_buck, *p_is64;
    cudaGetSymbolAddress(&p_qh, g_qh);
    cudaGetSymbolAddress(&p_kh, g_kh);
    cudaGetSymbolAddress(&p_vh, g_vh);
    cudaGetSymbolAddress(&p_s, g_s);
    cudaGetSymbolAddress(&p_h, g_h);
    cudaGetSymbolAddress(&p_xch, g_xch);
    cudaGetSymbolAddress(&p_wch, g_wch);
    cudaGetSymbolAddress(&p_wch2, g_wch2);
    cudaGetSymbolAddress(&p_deg, g_deg);
    cudaGetSymbolAddress(&p_buck, g_buck);
    cudaGetSymbolAddress(&p_is64, g_is64);

    __half* qh  = (__half*)p_qh;
    __half* kh  = (__half*)p_kh;
    __half* vh  = (__half*)p_vh;
    float*  s   = (float*)p_s;
    float*  h   = (float*)p_h;
    __half* xh  = (__half*)p_xch;
    __half* wh  = (__half*)p_wch;
    __half* wh2 = (__half*)p_wch2;
    float*  bkk = (float*)p_buck;

    cudaFuncSetAttribute(gemm4_f16_kernel<HID, IN_DIM>,
                         cudaFuncAttributeMaxDynamicSharedMemorySize, GEMM_SMEM_BYTES);
    cudaFuncSetAttribute(gemm4_f16_kernel<OUT_DIM, HID>,
                         cudaFuncAttributeMaxDynamicSharedMemorySize, GEMM_SMEM_BYTES);

    // ---- fork a side stream for the CSR build (R13-proven structure) ----
    cudaStream_t s2;
    cudaStreamCreateWithFlags(&s2, cudaStreamNonBlocking);
    cudaEvent_t evFork, evJoin;
    cudaEventCreateWithFlags(&evFork, cudaEventDisableTiming);
    cudaEventCreateWithFlags(&evJoin, cudaEventDisableTiming);

    cudaEventRecord(evFork, 0);
    cudaStreamWaitEvent(s2, evFork, 0);

    cudaMemsetAsync(p_is64, 0xFF, sizeof(int), s2);
    detect_idx_kernel<<<1024, 256, 0, s2>>>((const long long*)ei);
    cudaMemsetAsync(p_deg, 0, N_NODES * sizeof(int), s2);
    cvt_count_kernel<<<2048, 256, 0, s2>>>(ei);
    scan_offsets_kernel<<<1, 1024, 0, s2>>>();
    fill_csr_kernel<<<2048, 256, 0, s2>>>();
    cudaEventRecord(evJoin, s2);

    // main stream: converts + layer-1 GEMM (overlaps with CSR build)
    cudaMemsetAsync(p_buck, 0, 256 * sizeof(float), 0);
    cvt_f2h_kernel<<<2048, 256>>>(x, xh, N_NODES * IN_DIM);
    {
        dim3 g(256, 4);
        cvtT4_f2h_kernel<<<g, 256>>>(Wq1, Wk1, Wv1, Ws1, wh, IN_DIM, HID);
    }
    {
        dim3 g(128, 4);
        cvtT4_f2h_kernel<<<g, 256>>>(Wq2, Wk2, Wv2, Ws2, wh2, HID, OUT_DIM);
    }
    {
        dim3 grid((N_NODES + 127) / 128, HID / 128, 4);
        gemm4_f16_kernel<HID, IN_DIM><<<grid, 256, GEMM_SMEM_BYTES>>>(
            xh, wh, bq1, bk1, bv1, bs1, qh, kh, vh, s, N_NODES);
    }

    cudaStreamWaitEvent(0, evJoin, 0);

    edge_fused_kernel<HID, 8, 64><<<N_NODES, 256>>>(qh, kh, vh, s, h, bkk, 1.0f / 16.0f);
    normalize_elu_h_kernel<<<2048, 256>>>(h, ga1, be1, xh, bkk, HID - 1, (long)N_NODES * HID);

    // ---- layer 2 ----
    {
        dim3 grid((N_NODES + 127) / 128, OUT_DIM / 128, 4);
        gemm4_f16_kernel<OUT_DIM, HID><<<grid, 256, GEMM_SMEM_BYTES>>>(
            xh, wh2, bq2, bk2, bv2, bs2, qh, kh, vh, s, N_NODES);
    }
    edge_fused_kernel<OUT_DIM, 8, 64><<<N_NODES, 256>>>(qh, kh, vh, s, h, bkk + 128,
                                                        0.08838834764831845f);
    normalize_f_kernel<<<2048, 256>>>(h, ga2, be2, out, bkk + 128, OUT_DIM - 1,
                                      (long)N_NODES * OUT_DIM);

    cudaEventDestroy(evFork);
    cudaEventDestroy(evJoin);
    cudaStreamDestroy(s2);
}